// round 15
// baseline (speedup 1.0000x reference)
#include <cuda_runtime.h>
#include <cuda_fp16.h>
#include <cstdint>
#include <math.h>

// Problem constants
#define NB   2
#define TT   4096
#define NH   16
#define ND   64
#define HD   1024
#define DMOD 1024
#define MROWS (NB*TT)       // 8192
#define PHASE_SCALE 10.0f
#define LCH  32             // chunk length for the scan
#define NCH  128            // number of chunks (LCH*NCH == TT)
#define GK   1024
#define GN   1024

// ---------------- scratch (device globals; no allocs allowed) ----------------
__device__ float  g_K [MROWS * HD];
__device__ float  g_V [MROWS * HD];
__device__ float4 g_part[NB * NH * NCH * ND];
__device__ unsigned short g_ahi[MROWS * HD];     // fp16 hi of A operand (x / OH)
__device__ unsigned short g_alo[MROWS * HD];     // fp16 lo * 256 (x only; K GEMM)
__device__ unsigned short g_wT[6][HD * DMOD];    // WkT hi/lo, WvT hi, WoT hi

// ---------------- PTX helpers (baseline sm_80+ features only) ----------------
__device__ __forceinline__ uint32_t s2u(const void* p) {
    uint32_t a;
    asm("{ .reg .u64 t; cvta.to.shared.u64 t, %1; cvt.u32.u64 %0, t; }" : "=r"(a) : "l"(p));
    return a;
}
__device__ __forceinline__ void cp16(uint32_t s, const void* g) {
    asm volatile("cp.async.cg.shared.global [%0], [%1], 16;" :: "r"(s), "l"(g));
}
__device__ __forceinline__ void cp_commit() {
    asm volatile("cp.async.commit_group;" ::: "memory");
}
template <int N>
__device__ __forceinline__ void cp_wait() {
    asm volatile("cp.async.wait_group %0;" :: "n"(N) : "memory");
}
__device__ __forceinline__ void ldsm4(uint32_t* r, uint32_t addr) {
    asm volatile("ldmatrix.sync.aligned.m8n8.x4.shared.b16 {%0,%1,%2,%3}, [%4];"
        : "=r"(r[0]), "=r"(r[1]), "=r"(r[2]), "=r"(r[3]) : "r"(addr));
}
__device__ __forceinline__ void mma_f32(float* c, const uint32_t* a, const uint32_t* b) {
    asm volatile("mma.sync.aligned.m16n8k16.row.col.f32.f16.f16.f32 "
        "{%0,%1,%2,%3}, {%4,%5,%6,%7}, {%8,%9}, {%0,%1,%2,%3};"
        : "+f"(c[0]), "+f"(c[1]), "+f"(c[2]), "+f"(c[3])
        : "r"(a[0]), "r"(a[1]), "r"(a[2]), "r"(a[3]), "r"(b[0]), "r"(b[1]));
}
__device__ __forceinline__ void mma_f16(uint32_t* c, const uint32_t* a, const uint32_t* b) {
    asm volatile("mma.sync.aligned.m16n8k16.row.col.f16.f16.f16.f16 "
        "{%0,%1}, {%2,%3,%4,%5}, {%6,%7}, {%0,%1};"
        : "+r"(c[0]), "+r"(c[1])
        : "r"(a[0]), "r"(a[1]), "r"(a[2]), "r"(a[3]), "r"(b[0]), "r"(b[1]));
}

#define BM 128
#define BN 128
#define BK 32
#define ROWB 80                       // 64B data + 16B pad
#define TILE_B  (BM * ROWB)           // 10240 B
#define NIT (GK / BK)                 // 32

// ---------------------------------------------------------------------------
// FUSED K+V GEMM, one 1024-CTA launch:
//   blockIdx.z==0: C_K = A @ Wk^T, 3 terms (phase-sensitive, x10 amplified)
//   blockIdx.z==1: C_V = A @ Wv^T, 1 term  (linear; ~1.4e-4 rms error ok)
// K: hi*hi (f32acc) + [hi*lo' + lo'*hi] (f16acc), lo' = lo*256.
// 4 tiles/stage (A, Alo, Bhi, Blo; V uses only A, Bhi), 2 stages.
// ---------------------------------------------------------------------------
#define STAGE4 (4 * TILE_B)
#define GEMM_SMEM_KV (2 * STAGE4)     // 81920 B

__global__ __launch_bounds__(256, 2)
void gemm_kv(const unsigned short* __restrict__ Ahi,
             const unsigned short* __restrict__ Alo,
             const unsigned short* __restrict__ Bk_hi,
             const unsigned short* __restrict__ Bk_lo,
             const unsigned short* __restrict__ Bv_hi,
             float* __restrict__ CK,
             float* __restrict__ CV)
{
    extern __shared__ __align__(128) unsigned char smem[];
    const uint32_t sb = s2u(smem);

    const int tid  = threadIdx.x;
    const int lane = tid & 31;
    const int warp = tid >> 5;
    const int bm = blockIdx.y * BM;
    const int bn = blockIdx.x * BN;
    const bool t3 = (blockIdx.z == 0);      // K path: 3 terms
    const int m0 = (warp >> 2) * 64;
    const int n0 = (warp & 3) * 32;

    const unsigned short* Bhi = t3 ? Bk_hi : Bv_hi;
    float* C = t3 ? CK : CV;

    const unsigned short* srcs[4] = {
        Ahi + (size_t)bm * GK, Alo + (size_t)bm * GK,
        Bhi + (size_t)bn * GK, Bk_lo + (size_t)bn * GK };

    const int r0 = (tid + 0)   >> 2, c0i = (tid + 0)   & 3;
    const int r1 = (tid + 256) >> 2, c1i = (tid + 256) & 3;
    const uint32_t so0 = r0 * ROWB + c0i * 16;
    const uint32_t so1 = r1 * ROWB + c1i * 16;
    const size_t go0 = (size_t)r0 * GK + c0i * 8;
    const size_t go1 = (size_t)r1 * GK + c1i * 8;

    auto load_stage = [&](int s, int k0) {
        uint32_t base = sb + s * STAGE4;
        #pragma unroll
        for (int t = 0; t < 4; t++) {
            if (!t3 && (t == 1 || t == 3)) continue;  // V: only Ahi, Bhi
            cp16(base + t * TILE_B + so0, srcs[t] + go0 + k0);
            cp16(base + t * TILE_B + so1, srcs[t] + go1 + k0);
        }
        cp_commit();
    };

    float acc[4][4][4];
    #pragma unroll
    for (int i = 0; i < 4; i++)
        #pragma unroll
        for (int j = 0; j < 4; j++)
            #pragma unroll
            for (int k = 0; k < 4; k++) acc[i][j][k] = 0.f;
    uint32_t cacc[4][4][2];
    #pragma unroll
    for (int i = 0; i < 4; i++)
        #pragma unroll
        for (int j = 0; j < 4; j++) { cacc[i][j][0] = 0u; cacc[i][j][1] = 0u; }

    const uint32_t a_off = (m0 + (lane & 15)) * ROWB + (lane >> 4) * 16;
    const uint32_t b_off = (n0 + (lane >> 4) * 8 + (lane & 7)) * ROWB
                         + ((lane >> 3) & 1) * 16;

    load_stage(0, 0);

    #pragma unroll 2
    for (int it = 0; it < NIT; it++) {
        cp_wait<0>();
        __syncthreads();
        if (it + 1 < NIT) load_stage((it + 1) & 1, (it + 1) * BK);

        const uint32_t stg = sb + (it & 1) * STAGE4;
        const uint32_t sAh = stg + a_off;
        const uint32_t sAl = stg + TILE_B + a_off;
        const uint32_t sBh = stg + 2 * TILE_B + b_off;
        const uint32_t sBl = stg + 3 * TILE_B + b_off;

        #pragma unroll
        for (int kk = 0; kk < 2; kk++) {
            const uint32_t kb = kk * 32;
            uint32_t bh[8];
            ldsm4(bh + 0, sBh + kb);
            ldsm4(bh + 4, sBh + kb + 16 * ROWB);
            uint32_t bl[8];
            if (t3) {
                ldsm4(bl + 0, sBl + kb);
                ldsm4(bl + 4, sBl + kb + 16 * ROWB);
            }
            #pragma unroll
            for (int mt = 0; mt < 4; mt++) {
                uint32_t ah[4];
                ldsm4(ah, sAh + kb + mt * (16 * ROWB));
                #pragma unroll
                for (int nt = 0; nt < 4; nt++)       // hi*hi -> f32 acc
                    mma_f32(acc[mt][nt], ah, bh + (nt >> 1) * 4 + (nt & 1) * 2);
                if (t3) {
                    #pragma unroll
                    for (int nt = 0; nt < 4; nt++)   // hi*lo' -> f16 acc
                        mma_f16(cacc[mt][nt], ah, bl + (nt >> 1) * 4 + (nt & 1) * 2);
                    uint32_t al[4];
                    ldsm4(al, sAl + kb + mt * (16 * ROWB));
                    #pragma unroll
                    for (int nt = 0; nt < 4; nt++)   // lo'*hi -> f16 acc
                        mma_f16(cacc[mt][nt], al, bh + (nt >> 1) * 4 + (nt & 1) * 2);
                }
            }
        }
    }

    const float cs = 1.0f / 256.0f;
    #pragma unroll
    for (int mt = 0; mt < 4; mt++) {
        const int m = bm + m0 + mt * 16 + (lane >> 2);
        #pragma unroll
        for (int nt = 0; nt < 4; nt++) {
            const int n = bn + n0 + nt * 8 + (lane & 3) * 2;
            if (t3) {
                float2 c0 = __half22float2(*(__half2*)&cacc[mt][nt][0]);
                float2 c1 = __half22float2(*(__half2*)&cacc[mt][nt][1]);
                *(float2*)&C[(size_t)m * GN + n] =
                    make_float2(acc[mt][nt][0] + cs * c0.x,
                                acc[mt][nt][1] + cs * c0.y);
                *(float2*)&C[(size_t)(m + 8) * GN + n] =
                    make_float2(acc[mt][nt][2] + cs * c1.x,
                                acc[mt][nt][3] + cs * c1.y);
            } else {
                *(float2*)&C[(size_t)m * GN + n] =
                    make_float2(acc[mt][nt][0], acc[mt][nt][1]);
                *(float2*)&C[(size_t)(m + 8) * GN + n] =
                    make_float2(acc[mt][nt][2], acc[mt][nt][3]);
            }
        }
    }
}

// ---------------------------------------------------------------------------
// Wo GEMM: 1-term fp16 (hi*hi -> f32acc), 2 tiles/stage, 3 stages, wait 1.
// ---------------------------------------------------------------------------
#define STAGE2 (2 * TILE_B)
#define GEMM_SMEM_T1 (3 * STAGE2)     // 61440 B

__global__ __launch_bounds__(256, 2)
void gemm_t1(const unsigned short* __restrict__ Ahi,
             const unsigned short* __restrict__ Bhi,
             float* __restrict__ C)
{
    extern __shared__ __align__(128) unsigned char smem[];
    const uint32_t sb = s2u(smem);

    const int tid  = threadIdx.x;
    const int lane = tid & 31;
    const int warp = tid >> 5;
    const int bm = blockIdx.y * BM;
    const int bn = blockIdx.x * BN;
    const int m0 = (warp >> 2) * 64;
    const int n0 = (warp & 3) * 32;

    const unsigned short* srcs[2] = {
        Ahi + (size_t)bm * GK, Bhi + (size_t)bn * GK };

    const int r0 = (tid + 0)   >> 2, c0i = (tid + 0)   & 3;
    const int r1 = (tid + 256) >> 2, c1i = (tid + 256) & 3;
    const uint32_t so0 = r0 * ROWB + c0i * 16;
    const uint32_t so1 = r1 * ROWB + c1i * 16;
    const size_t go0 = (size_t)r0 * GK + c0i * 8;
    const size_t go1 = (size_t)r1 * GK + c1i * 8;

    auto load_stage = [&](int s, int k0) {
        uint32_t base = sb + s * STAGE2;
        #pragma unroll
        for (int t = 0; t < 2; t++) {
            cp16(base + t * TILE_B + so0, srcs[t] + go0 + k0);
            cp16(base + t * TILE_B + so1, srcs[t] + go1 + k0);
        }
        cp_commit();
    };

    float acc[4][4][4];
    #pragma unroll
    for (int i = 0; i < 4; i++)
        #pragma unroll
        for (int j = 0; j < 4; j++)
            #pragma unroll
            for (int k = 0; k < 4; k++) acc[i][j][k] = 0.f;

    const uint32_t a_off = (m0 + (lane & 15)) * ROWB + (lane >> 4) * 16;
    const uint32_t b_off = (n0 + (lane >> 4) * 8 + (lane & 7)) * ROWB
                         + ((lane >> 3) & 1) * 16;

    load_stage(0, 0);
    load_stage(1, BK);

    int s_cur = 0;
    for (int it = 0; it < NIT; it++) {
        cp_wait<1>();
        __syncthreads();
        if (it + 2 < NIT) {
            int s_nx = s_cur + 2; if (s_nx >= 3) s_nx -= 3;
            load_stage(s_nx, (it + 2) * BK);
        }

        const uint32_t stg = sb + s_cur * STAGE2;
        const uint32_t sAh = stg + a_off;
        const uint32_t sBh = stg + TILE_B + b_off;

        #pragma unroll
        for (int kk = 0; kk < 2; kk++) {
            const uint32_t kb = kk * 32;
            uint32_t bh[8];
            ldsm4(bh + 0, sBh + kb);
            ldsm4(bh + 4, sBh + kb + 16 * ROWB);
            #pragma unroll
            for (int mt = 0; mt < 4; mt++) {
                uint32_t ah[4];
                ldsm4(ah, sAh + kb + mt * (16 * ROWB));
                #pragma unroll
                for (int nt = 0; nt < 4; nt++)
                    mma_f32(acc[mt][nt], ah, bh + (nt >> 1) * 4 + (nt & 1) * 2);
            }
        }
        if (++s_cur == 3) s_cur = 0;
    }

    #pragma unroll
    for (int mt = 0; mt < 4; mt++) {
        const int m = bm + m0 + mt * 16 + (lane >> 2);
        #pragma unroll
        for (int nt = 0; nt < 4; nt++) {
            const int n = bn + n0 + nt * 8 + (lane & 3) * 2;
            *(float2*)&C[(size_t)m * GN + n] =
                make_float2(acc[mt][nt][0], acc[mt][nt][1]);
            *(float2*)&C[(size_t)(m + 8) * GN + n] =
                make_float2(acc[mt][nt][2], acc[mt][nt][3]);
        }
    }
}

// ---------------------------------------------------------------------------
// fp32 -> fp16 hi + (lo*256) split helpers
// ---------------------------------------------------------------------------
__device__ __forceinline__ unsigned short f16_hi(float x, float& rem) {
    __half h = __float2half_rn(x);
    rem = x - __half2float(h);
    return __half_as_ushort(h);
}
__device__ __forceinline__ unsigned short f16_lo256(float rem) {
    return __half_as_ushort(__float2half_rn(rem * 256.0f));
}

__global__ void split_hilo(const float* __restrict__ src,
                           unsigned short* __restrict__ hi,
                           unsigned short* __restrict__ lo, int n4)
{
    int i = blockIdx.x * blockDim.x + threadIdx.x;
    if (i >= n4) return;
    float4 v = ((const float4*)src)[i];
    float r0, r1, r2, r3;
    unsigned short h0 = f16_hi(v.x, r0), h1 = f16_hi(v.y, r1);
    unsigned short h2 = f16_hi(v.z, r2), h3 = f16_hi(v.w, r3);
    ((uint2*)hi)[i] = make_uint2((uint32_t)h0 | ((uint32_t)h1 << 16),
                                (uint32_t)h2 | ((uint32_t)h3 << 16));
    unsigned short l0 = f16_lo256(r0), l1 = f16_lo256(r1);
    unsigned short l2 = f16_lo256(r2), l3 = f16_lo256(r3);
    ((uint2*)lo)[i] = make_uint2((uint32_t)l0 | ((uint32_t)l1 << 16),
                                (uint32_t)l2 | ((uint32_t)l3 << 16));
}

// W [K,N] fp32 -> WT [N,K] fp16; lo written only for Wk (z==0)
__global__ void wsplitT3(const float* __restrict__ W0,
                         const float* __restrict__ W1,
                         const float* __restrict__ W2)
{
    __shared__ float tile[32][33];
    const float* W = (blockIdx.z == 0) ? W0 : (blockIdx.z == 1) ? W1 : W2;
    unsigned short* hiT = &g_wT[2 * blockIdx.z][0];
    unsigned short* loT = &g_wT[2 * blockIdx.z + 1][0];
    int n0 = blockIdx.x * 32, k0 = blockIdx.y * 32;
    int tx = threadIdx.x, ty = threadIdx.y;
    for (int r = ty; r < 32; r += 8)
        tile[r][tx] = W[(size_t)(k0 + r) * GN + n0 + tx];
    __syncthreads();
    for (int r = ty; r < 32; r += 8) {
        float v = tile[tx][r];
        size_t o = (size_t)(n0 + r) * GK + k0 + tx;
        float rem;
        hiT[o] = f16_hi(v, rem);
        if (blockIdx.z == 0) loT[o] = f16_lo256(rem);
    }
}

// ---------------------------------------------------------------------------
// Scan pass A: per-chunk partial complex sums.
// ---------------------------------------------------------------------------
__global__ void scan_partials(const float* __restrict__ freqs)
{
    const int tid = threadIdx.x;
    const int d   = tid & 63;
    const int sub = tid >> 6;
    const int bh  = blockIdx.x >> 5;
    const int cg  = blockIdx.x & 31;
    const int c   = cg * 4 + sub;
    const int b   = bh >> 4;
    const int h   = bh & 15;
    const int t0 = c * LCH;
    const int hd = h * ND + d;

    const float f = freqs[hd];

    float pc = 0.f, ps = 0.f;
    if (t0 > 0) {
        float th = PHASE_SCALE * g_K[((size_t)(b * TT + t0 - 1)) * HD + hd];
        __sincosf(th, &ps, &pc);
    }

    float Pre = 0.f, Pim = 0.f, Are = 0.f, Aim = 0.f;
    size_t base = ((size_t)(b * TT + t0)) * HD + hd;
    for (int i = 0; i < LCH; i++) {
        float v  = g_V[base];
        float kr = g_K[base];
        base += HD;
        Are += v * pc;
        Aim -= v * ps;
        float ks, kc;
        __sincosf(PHASE_SCALE * kr, &ks, &kc);
        pc = kc; ps = ks;
        float sr, cr;
        sincosf((float)(t0 + i) * f, &sr, &cr);
        Pre += v * cr;
        Pim += v * sr;
    }
    g_part[((size_t)bh * NCH + c) * ND + d] = make_float4(Pre, Pim, Are, Aim);
}

// ---------------------------------------------------------------------------
// Convert g_part to EXCLUSIVE prefix along the chunk axis (in place).
// One warp per (bh, d) sequence: 32*64 = 2048 warps. Warp-shfl scan,
// 4 rounds of 32 chunks.
// ---------------------------------------------------------------------------
__global__ void part_prefix()
{
    const int gw   = (blockIdx.x * blockDim.x + threadIdx.x) >> 5;  // 0..2047
    const int lane = threadIdx.x & 31;
    if (gw >= 32 * ND) return;
    const int bh = gw >> 6;
    const int d  = gw & 63;
    float4* p = g_part + (size_t)bh * NCH * ND + d;

    float4 carry = make_float4(0.f, 0.f, 0.f, 0.f);
    #pragma unroll
    for (int r = 0; r < 4; r++) {
        const int c = r * 32 + lane;
        float4 v = p[(size_t)c * ND];
        float4 incl = v;
        #pragma unroll
        for (int ofs = 1; ofs < 32; ofs <<= 1) {
            float ax = __shfl_up_sync(0xffffffffu, incl.x, ofs);
            float ay = __shfl_up_sync(0xffffffffu, incl.y, ofs);
            float az = __shfl_up_sync(0xffffffffu, incl.z, ofs);
            float aw = __shfl_up_sync(0xffffffffu, incl.w, ofs);
            if (lane >= ofs) { incl.x += ax; incl.y += ay; incl.z += az; incl.w += aw; }
        }
        float4 excl = make_float4(incl.x - v.x + carry.x, incl.y - v.y + carry.y,
                                  incl.z - v.z + carry.z, incl.w - v.w + carry.w);
        p[(size_t)c * ND] = excl;
        carry.x += __shfl_sync(0xffffffffu, incl.x, 31);
        carry.y += __shfl_sync(0xffffffffu, incl.y, 31);
        carry.z += __shfl_sync(0xffffffffu, incl.z, 31);
        carry.w += __shfl_sync(0xffffffffu, incl.w, 31);
    }
}

// ---------------------------------------------------------------------------
// Scan pass B: single exclusive-offset load + final gated output -> fp16 hi
// ---------------------------------------------------------------------------
__global__ void scan_final(const float* __restrict__ freqs,
                           const float* __restrict__ gate)
{
    const int tid = threadIdx.x;
    const int d   = tid & 63;
    const int sub = tid >> 6;
    const int bh  = blockIdx.x >> 5;
    const int cg  = blockIdx.x & 31;
    const int c   = cg * 4 + sub;
    const int b   = bh >> 4;
    const int h   = bh & 15;
    const int hd  = h * ND + d;

    const float f  = freqs[hd];
    const float g0 = gate[2 * h];
    const float g1 = gate[2 * h + 1];
    const int t0 = c * LCH;

    // exclusive prefix precomputed in place by part_prefix
    float4 off = g_part[((size_t)bh * NCH + c) * ND + d];
    float Pre = off.x, Pim = off.y, Are = off.z, Aim = off.w;

    float pc = 0.f, ps = 0.f;
    if (t0 > 0) {
        float th = PHASE_SCALE * g_K[((size_t)(b * TT + t0 - 1)) * HD + hd];
        __sincosf(th, &ps, &pc);
    }

    size_t base = ((size_t)(b * TT + t0)) * HD + hd;
    for (int i = 0; i < LCH; i++) {
        float v  = g_V[base];
        float kr = g_K[base];
        Are += v * pc;
        Aim -= v * ps;
        float ks, kc;
        __sincosf(PHASE_SCALE * kr, &ks, &kc);
        float oa = Are * kc - Aim * ks;
        pc = kc; ps = ks;
        float sr, cr;
        sincosf((float)(t0 + i) * f, &sr, &cr);
        Pre += v * cr;
        Pim += v * sr;
        float op = Pre * cr + Pim * sr;
        int t = t0 + i;
        float o = (g0 * op + g1 * oa) * rsqrtf((float)(t + 1));
        g_ahi[base] = __half_as_ushort(__float2half_rn(o));
        base += HD;
    }
}

// ---------------------------------------------------------------------------
extern "C" void kernel_launch(void* const* d_in, const int* in_sizes, int n_in,
                              void* d_out, int out_size)
{
    const float* x     = (const float*)d_in[0];
    const float* Wk    = (const float*)d_in[1];
    const float* Wv    = (const float*)d_in[2];
    const float* Wo    = (const float*)d_in[3];
    const float* gate  = (const float*)d_in[4];
    const float* freqs = (const float*)d_in[5];
    float* out = (float*)d_out;

    float *pK, *pV;
    unsigned short *pahi, *palo, *pwT;
    cudaGetSymbolAddress((void**)&pK,   g_K);
    cudaGetSymbolAddress((void**)&pV,   g_V);
    cudaGetSymbolAddress((void**)&pahi, g_ahi);
    cudaGetSymbolAddress((void**)&palo, g_alo);
    cudaGetSymbolAddress((void**)&pwT,  g_wT);

    cudaFuncSetAttribute(gemm_kv,
                         cudaFuncAttributeMaxDynamicSharedMemorySize, GEMM_SMEM_KV);
    cudaFuncSetAttribute(gemm_t1,
                         cudaFuncAttributeMaxDynamicSharedMemorySize, GEMM_SMEM_T1);

    const int WSZ = HD * DMOD;
    unsigned short* wkh = pwT + 0*WSZ; unsigned short* wkl = pwT + 1*WSZ;
    unsigned short* wvh = pwT + 2*WSZ;
    unsigned short* woh = pwT + 4*WSZ;

    const int n4 = MROWS * HD / 4;
    split_hilo<<<(n4 + 255) / 256, 256>>>(x, pahi, palo, n4);
    wsplitT3<<<dim3(32, 32, 3), dim3(32, 8)>>>(Wk, Wv, Wo);

    // fused K (3-term) + V (1-term) in one 1024-CTA launch
    dim3 gkv(GN / BN, MROWS / BM, 2);
    gemm_kv<<<gkv, 256, GEMM_SMEM_KV>>>(pahi, palo, wkh, wkl, wvh, pK, pV);

    int nscan = NB * NH * (NCH / 4);     // 1024
    scan_partials<<<nscan, 256>>>(freqs);
    part_prefix<<<256, 256>>>();                 // 2048 warps
    scan_final<<<nscan, 256>>>(freqs, gate);     // writes g_ahi only

    dim3 go(GN / BN, MROWS / BM);
    gemm_t1<<<go, 256, GEMM_SMEM_T1>>>(pahi, woh, out);   // Wo: 1-term
}

// round 16
// speedup vs baseline: 1.5626x; 1.5626x over previous
#include <cuda_runtime.h>
#include <cuda_fp16.h>
#include <cstdint>
#include <math.h>

// Problem constants
#define NB   2
#define TT   4096
#define NH   16
#define ND   64
#define HD   1024
#define DMOD 1024
#define MROWS (NB*TT)       // 8192
#define PHASE_SCALE 10.0f
#define LCH  32             // chunk length for the scan
#define NCH  128            // number of chunks (LCH*NCH == TT)
#define GK   1024
#define GN   1024

// ---------------- scratch (device globals; no allocs allowed) ----------------
__device__ float  g_K [MROWS * HD];
__device__ float  g_V [MROWS * HD];
__device__ float4 g_part[NB * NH * NCH * ND];
__device__ unsigned short g_ahi[MROWS * HD];     // fp16 hi of A operand (x / OH)
__device__ unsigned short g_alo[MROWS * HD];     // fp16 lo * 256 (x only; K GEMM)
__device__ unsigned short g_wT[6][HD * DMOD];    // WkT hi/lo, WvT hi, WoT hi

// ---------------- PTX helpers (baseline sm_80+ features only) ----------------
__device__ __forceinline__ uint32_t s2u(const void* p) {
    uint32_t a;
    asm("{ .reg .u64 t; cvta.to.shared.u64 t, %1; cvt.u32.u64 %0, t; }" : "=r"(a) : "l"(p));
    return a;
}
__device__ __forceinline__ void cp16(uint32_t s, const void* g) {
    asm volatile("cp.async.cg.shared.global [%0], [%1], 16;" :: "r"(s), "l"(g));
}
__device__ __forceinline__ void cp_commit() {
    asm volatile("cp.async.commit_group;" ::: "memory");
}
template <int N>
__device__ __forceinline__ void cp_wait() {
    asm volatile("cp.async.wait_group %0;" :: "n"(N) : "memory");
}
__device__ __forceinline__ void ldsm4(uint32_t* r, uint32_t addr) {
    asm volatile("ldmatrix.sync.aligned.m8n8.x4.shared.b16 {%0,%1,%2,%3}, [%4];"
        : "=r"(r[0]), "=r"(r[1]), "=r"(r[2]), "=r"(r[3]) : "r"(addr));
}
__device__ __forceinline__ void mma_f32(float* c, const uint32_t* a, const uint32_t* b) {
    asm volatile("mma.sync.aligned.m16n8k16.row.col.f32.f16.f16.f32 "
        "{%0,%1,%2,%3}, {%4,%5,%6,%7}, {%8,%9}, {%0,%1,%2,%3};"
        : "+f"(c[0]), "+f"(c[1]), "+f"(c[2]), "+f"(c[3])
        : "r"(a[0]), "r"(a[1]), "r"(a[2]), "r"(a[3]), "r"(b[0]), "r"(b[1]));
}
__device__ __forceinline__ void mma_f16(uint32_t* c, const uint32_t* a, const uint32_t* b) {
    asm volatile("mma.sync.aligned.m16n8k16.row.col.f16.f16.f16.f16 "
        "{%0,%1}, {%2,%3,%4,%5}, {%6,%7}, {%0,%1};"
        : "+r"(c[0]), "+r"(c[1])
        : "r"(a[0]), "r"(a[1]), "r"(a[2]), "r"(a[3]), "r"(b[0]), "r"(b[1]));
}

#define BM 128
#define BN 128
#define BK 32
#define ROWB 80                       // 64B data + 16B pad
#define TILE_B  (BM * ROWB)           // 10240 B
#define NIT (GK / BK)                 // 32

// ---------------------------------------------------------------------------
// K GEMM: 3-term fp16 (round-13 known-good code, no data-dependent branches)
// hi*hi (f32acc) + [hi*lo' + lo'*hi] (f16acc), lo' = lo*256.
// 4 tiles/stage (Ahi, Alo, Bhi, Blo), 2 stages, wait_group 0.
// ---------------------------------------------------------------------------
#define STAGE4 (4 * TILE_B)
#define GEMM_SMEM_T3 (2 * STAGE4)     // 81920 B

__global__ __launch_bounds__(256, 2)
void gemm_t3(const unsigned short* __restrict__ Ahi,
             const unsigned short* __restrict__ Alo,
             const unsigned short* __restrict__ Bhi,
             const unsigned short* __restrict__ Blo,
             float* __restrict__ C)
{
    extern __shared__ __align__(128) unsigned char smem[];
    const uint32_t sb = s2u(smem);

    const int tid  = threadIdx.x;
    const int lane = tid & 31;
    const int warp = tid >> 5;
    const int bm = blockIdx.y * BM;
    const int bn = blockIdx.x * BN;
    const int m0 = (warp >> 2) * 64;
    const int n0 = (warp & 3) * 32;

    const unsigned short* srcs[4] = {
        Ahi + (size_t)bm * GK, Alo + (size_t)bm * GK,
        Bhi + (size_t)bn * GK, Blo + (size_t)bn * GK };

    const int r0 = (tid + 0)   >> 2, c0i = (tid + 0)   & 3;
    const int r1 = (tid + 256) >> 2, c1i = (tid + 256) & 3;
    const uint32_t so0 = r0 * ROWB + c0i * 16;
    const uint32_t so1 = r1 * ROWB + c1i * 16;
    const size_t go0 = (size_t)r0 * GK + c0i * 8;
    const size_t go1 = (size_t)r1 * GK + c1i * 8;

    auto load_stage = [&](int s, int k0) {
        uint32_t base = sb + s * STAGE4;
        #pragma unroll
        for (int t = 0; t < 4; t++) {
            cp16(base + t * TILE_B + so0, srcs[t] + go0 + k0);
            cp16(base + t * TILE_B + so1, srcs[t] + go1 + k0);
        }
        cp_commit();
    };

    float acc[4][4][4];
    #pragma unroll
    for (int i = 0; i < 4; i++)
        #pragma unroll
        for (int j = 0; j < 4; j++)
            #pragma unroll
            for (int k = 0; k < 4; k++) acc[i][j][k] = 0.f;
    uint32_t cacc[4][4][2];
    #pragma unroll
    for (int i = 0; i < 4; i++)
        #pragma unroll
        for (int j = 0; j < 4; j++) { cacc[i][j][0] = 0u; cacc[i][j][1] = 0u; }

    const uint32_t a_off = (m0 + (lane & 15)) * ROWB + (lane >> 4) * 16;
    const uint32_t b_off = (n0 + (lane >> 4) * 8 + (lane & 7)) * ROWB
                         + ((lane >> 3) & 1) * 16;

    load_stage(0, 0);

    #pragma unroll 2
    for (int it = 0; it < NIT; it++) {
        cp_wait<0>();
        __syncthreads();
        if (it + 1 < NIT) load_stage((it + 1) & 1, (it + 1) * BK);

        const uint32_t stg = sb + (it & 1) * STAGE4;
        const uint32_t sAh = stg + a_off;
        const uint32_t sAl = stg + TILE_B + a_off;
        const uint32_t sBh = stg + 2 * TILE_B + b_off;
        const uint32_t sBl = stg + 3 * TILE_B + b_off;

        #pragma unroll
        for (int kk = 0; kk < 2; kk++) {
            const uint32_t kb = kk * 32;
            uint32_t bh[8], bl[8];
            ldsm4(bh + 0, sBh + kb);
            ldsm4(bh + 4, sBh + kb + 16 * ROWB);
            ldsm4(bl + 0, sBl + kb);
            ldsm4(bl + 4, sBl + kb + 16 * ROWB);
            #pragma unroll
            for (int mt = 0; mt < 4; mt++) {
                uint32_t ah[4];
                ldsm4(ah, sAh + kb + mt * (16 * ROWB));
                #pragma unroll
                for (int nt = 0; nt < 4; nt++)       // hi*hi -> f32 acc
                    mma_f32(acc[mt][nt], ah, bh + (nt >> 1) * 4 + (nt & 1) * 2);
                #pragma unroll
                for (int nt = 0; nt < 4; nt++)       // hi*lo' -> f16 acc
                    mma_f16(cacc[mt][nt], ah, bl + (nt >> 1) * 4 + (nt & 1) * 2);
                uint32_t al[4];
                ldsm4(al, sAl + kb + mt * (16 * ROWB));
                #pragma unroll
                for (int nt = 0; nt < 4; nt++)       // lo'*hi -> f16 acc
                    mma_f16(cacc[mt][nt], al, bh + (nt >> 1) * 4 + (nt & 1) * 2);
            }
        }
    }

    const float cs = 1.0f / 256.0f;
    #pragma unroll
    for (int mt = 0; mt < 4; mt++) {
        const int m = bm + m0 + mt * 16 + (lane >> 2);
        #pragma unroll
        for (int nt = 0; nt < 4; nt++) {
            const int n = bn + n0 + nt * 8 + (lane & 3) * 2;
            float2 c0 = __half22float2(*(__half2*)&cacc[mt][nt][0]);
            float2 c1 = __half22float2(*(__half2*)&cacc[mt][nt][1]);
            *(float2*)&C[(size_t)m * GN + n] =
                make_float2(acc[mt][nt][0] + cs * c0.x,
                            acc[mt][nt][1] + cs * c0.y);
            *(float2*)&C[(size_t)(m + 8) * GN + n] =
                make_float2(acc[mt][nt][2] + cs * c1.x,
                            acc[mt][nt][3] + cs * c1.y);
        }
    }
}

// ---------------------------------------------------------------------------
// 1-term GEMM (V, Wo): hi*hi -> f32acc. 2 tiles/stage, 3 stages, wait 1.
// Branch-free, minimal registers.
// ---------------------------------------------------------------------------
#define STAGE2 (2 * TILE_B)
#define GEMM_SMEM_T1 (3 * STAGE2)     // 61440 B

__global__ __launch_bounds__(256, 2)
void gemm_t1(const unsigned short* __restrict__ Ahi,
             const unsigned short* __restrict__ Bhi,
             float* __restrict__ C)
{
    extern __shared__ __align__(128) unsigned char smem[];
    const uint32_t sb = s2u(smem);

    const int tid  = threadIdx.x;
    const int lane = tid & 31;
    const int warp = tid >> 5;
    const int bm = blockIdx.y * BM;
    const int bn = blockIdx.x * BN;
    const int m0 = (warp >> 2) * 64;
    const int n0 = (warp & 3) * 32;

    const unsigned short* srcs[2] = {
        Ahi + (size_t)bm * GK, Bhi + (size_t)bn * GK };

    const int r0 = (tid + 0)   >> 2, c0i = (tid + 0)   & 3;
    const int r1 = (tid + 256) >> 2, c1i = (tid + 256) & 3;
    const uint32_t so0 = r0 * ROWB + c0i * 16;
    const uint32_t so1 = r1 * ROWB + c1i * 16;
    const size_t go0 = (size_t)r0 * GK + c0i * 8;
    const size_t go1 = (size_t)r1 * GK + c1i * 8;

    auto load_stage = [&](int s, int k0) {
        uint32_t base = sb + s * STAGE2;
        #pragma unroll
        for (int t = 0; t < 2; t++) {
            cp16(base + t * TILE_B + so0, srcs[t] + go0 + k0);
            cp16(base + t * TILE_B + so1, srcs[t] + go1 + k0);
        }
        cp_commit();
    };

    float acc[4][4][4];
    #pragma unroll
    for (int i = 0; i < 4; i++)
        #pragma unroll
        for (int j = 0; j < 4; j++)
            #pragma unroll
            for (int k = 0; k < 4; k++) acc[i][j][k] = 0.f;

    const uint32_t a_off = (m0 + (lane & 15)) * ROWB + (lane >> 4) * 16;
    const uint32_t b_off = (n0 + (lane >> 4) * 8 + (lane & 7)) * ROWB
                         + ((lane >> 3) & 1) * 16;

    load_stage(0, 0);
    load_stage(1, BK);

    int s_cur = 0;
    for (int it = 0; it < NIT; it++) {
        cp_wait<1>();
        __syncthreads();
        if (it + 2 < NIT) {
            int s_nx = s_cur + 2; if (s_nx >= 3) s_nx -= 3;
            load_stage(s_nx, (it + 2) * BK);
        }

        const uint32_t stg = sb + s_cur * STAGE2;
        const uint32_t sAh = stg + a_off;
        const uint32_t sBh = stg + TILE_B + b_off;

        #pragma unroll
        for (int kk = 0; kk < 2; kk++) {
            const uint32_t kb = kk * 32;
            uint32_t bh[8];
            ldsm4(bh + 0, sBh + kb);
            ldsm4(bh + 4, sBh + kb + 16 * ROWB);
            #pragma unroll
            for (int mt = 0; mt < 4; mt++) {
                uint32_t ah[4];
                ldsm4(ah, sAh + kb + mt * (16 * ROWB));
                #pragma unroll
                for (int nt = 0; nt < 4; nt++)
                    mma_f32(acc[mt][nt], ah, bh + (nt >> 1) * 4 + (nt & 1) * 2);
            }
        }
        if (++s_cur == 3) s_cur = 0;
    }

    #pragma unroll
    for (int mt = 0; mt < 4; mt++) {
        const int m = bm + m0 + mt * 16 + (lane >> 2);
        #pragma unroll
        for (int nt = 0; nt < 4; nt++) {
            const int n = bn + n0 + nt * 8 + (lane & 3) * 2;
            *(float2*)&C[(size_t)m * GN + n] =
                make_float2(acc[mt][nt][0], acc[mt][nt][1]);
            *(float2*)&C[(size_t)(m + 8) * GN + n] =
                make_float2(acc[mt][nt][2], acc[mt][nt][3]);
        }
    }
}

// ---------------------------------------------------------------------------
// fp32 -> fp16 hi + (lo*256) split helpers
// ---------------------------------------------------------------------------
__device__ __forceinline__ unsigned short f16_hi(float x, float& rem) {
    __half h = __float2half_rn(x);
    rem = x - __half2float(h);
    return __half_as_ushort(h);
}
__device__ __forceinline__ unsigned short f16_lo256(float rem) {
    return __half_as_ushort(__float2half_rn(rem * 256.0f));
}

__global__ void split_hilo(const float* __restrict__ src,
                           unsigned short* __restrict__ hi,
                           unsigned short* __restrict__ lo, int n4)
{
    int i = blockIdx.x * blockDim.x + threadIdx.x;
    if (i >= n4) return;
    float4 v = ((const float4*)src)[i];
    float r0, r1, r2, r3;
    unsigned short h0 = f16_hi(v.x, r0), h1 = f16_hi(v.y, r1);
    unsigned short h2 = f16_hi(v.z, r2), h3 = f16_hi(v.w, r3);
    ((uint2*)hi)[i] = make_uint2((uint32_t)h0 | ((uint32_t)h1 << 16),
                                (uint32_t)h2 | ((uint32_t)h3 << 16));
    unsigned short l0 = f16_lo256(r0), l1 = f16_lo256(r1);
    unsigned short l2 = f16_lo256(r2), l3 = f16_lo256(r3);
    ((uint2*)lo)[i] = make_uint2((uint32_t)l0 | ((uint32_t)l1 << 16),
                                (uint32_t)l2 | ((uint32_t)l3 << 16));
}

// W [K,N] fp32 -> WT [N,K] fp16; lo written only for Wk (z==0)
__global__ void wsplitT3(const float* __restrict__ W0,
                         const float* __restrict__ W1,
                         const float* __restrict__ W2)
{
    __shared__ float tile[32][33];
    const float* W = (blockIdx.z == 0) ? W0 : (blockIdx.z == 1) ? W1 : W2;
    unsigned short* hiT = &g_wT[2 * blockIdx.z][0];
    unsigned short* loT = &g_wT[2 * blockIdx.z + 1][0];
    int n0 = blockIdx.x * 32, k0 = blockIdx.y * 32;
    int tx = threadIdx.x, ty = threadIdx.y;
    for (int r = ty; r < 32; r += 8)
        tile[r][tx] = W[(size_t)(k0 + r) * GN + n0 + tx];
    __syncthreads();
    for (int r = ty; r < 32; r += 8) {
        float v = tile[tx][r];
        size_t o = (size_t)(n0 + r) * GK + k0 + tx;
        float rem;
        hiT[o] = f16_hi(v, rem);
        if (blockIdx.z == 0) loT[o] = f16_lo256(rem);
    }
}

// ---------------------------------------------------------------------------
// Scan pass A: per-chunk partial complex sums.
// ---------------------------------------------------------------------------
__global__ void scan_partials(const float* __restrict__ freqs)
{
    const int tid = threadIdx.x;
    const int d   = tid & 63;
    const int sub = tid >> 6;
    const int bh  = blockIdx.x >> 5;
    const int cg  = blockIdx.x & 31;
    const int c   = cg * 4 + sub;
    const int b   = bh >> 4;
    const int h   = bh & 15;
    const int t0 = c * LCH;
    const int hd = h * ND + d;

    const float f = freqs[hd];

    float pc = 0.f, ps = 0.f;
    if (t0 > 0) {
        float th = PHASE_SCALE * g_K[((size_t)(b * TT + t0 - 1)) * HD + hd];
        __sincosf(th, &ps, &pc);
    }

    float Pre = 0.f, Pim = 0.f, Are = 0.f, Aim = 0.f;
    size_t base = ((size_t)(b * TT + t0)) * HD + hd;
    for (int i = 0; i < LCH; i++) {
        float v  = g_V[base];
        float kr = g_K[base];
        base += HD;
        Are += v * pc;
        Aim -= v * ps;
        float ks, kc;
        __sincosf(PHASE_SCALE * kr, &ks, &kc);
        pc = kc; ps = ks;
        float sr, cr;
        sincosf((float)(t0 + i) * f, &sr, &cr);
        Pre += v * cr;
        Pim += v * sr;
    }
    g_part[((size_t)bh * NCH + c) * ND + d] = make_float4(Pre, Pim, Are, Aim);
}

// ---------------------------------------------------------------------------
// Convert g_part to EXCLUSIVE prefix along the chunk axis (in place).
// One warp per (bh, d) sequence: 32*64 = 2048 warps.
// ---------------------------------------------------------------------------
__global__ void part_prefix()
{
    const int gw   = (blockIdx.x * blockDim.x + threadIdx.x) >> 5;  // 0..2047
    const int lane = threadIdx.x & 31;
    if (gw >= 32 * ND) return;
    const int bh = gw >> 6;
    const int d  = gw & 63;
    float4* p = g_part + (size_t)bh * NCH * ND + d;

    float4 carry = make_float4(0.f, 0.f, 0.f, 0.f);
    #pragma unroll
    for (int r = 0; r < 4; r++) {
        const int c = r * 32 + lane;
        float4 v = p[(size_t)c * ND];
        float4 incl = v;
        #pragma unroll
        for (int ofs = 1; ofs < 32; ofs <<= 1) {
            float ax = __shfl_up_sync(0xffffffffu, incl.x, ofs);
            float ay = __shfl_up_sync(0xffffffffu, incl.y, ofs);
            float az = __shfl_up_sync(0xffffffffu, incl.z, ofs);
            float aw = __shfl_up_sync(0xffffffffu, incl.w, ofs);
            if (lane >= ofs) { incl.x += ax; incl.y += ay; incl.z += az; incl.w += aw; }
        }
        float4 excl = make_float4(incl.x - v.x + carry.x, incl.y - v.y + carry.y,
                                  incl.z - v.z + carry.z, incl.w - v.w + carry.w);
        p[(size_t)c * ND] = excl;
        carry.x += __shfl_sync(0xffffffffu, incl.x, 31);
        carry.y += __shfl_sync(0xffffffffu, incl.y, 31);
        carry.z += __shfl_sync(0xffffffffu, incl.z, 31);
        carry.w += __shfl_sync(0xffffffffu, incl.w, 31);
    }
}

// ---------------------------------------------------------------------------
// Scan pass B: single exclusive-offset load + final gated output -> fp16 hi
// ---------------------------------------------------------------------------
__global__ void scan_final(const float* __restrict__ freqs,
                           const float* __restrict__ gate)
{
    const int tid = threadIdx.x;
    const int d   = tid & 63;
    const int sub = tid >> 6;
    const int bh  = blockIdx.x >> 5;
    const int cg  = blockIdx.x & 31;
    const int c   = cg * 4 + sub;
    const int b   = bh >> 4;
    const int h   = bh & 15;
    const int hd  = h * ND + d;

    const float f  = freqs[hd];
    const float g0 = gate[2 * h];
    const float g1 = gate[2 * h + 1];
    const int t0 = c * LCH;

    float4 off = g_part[((size_t)bh * NCH + c) * ND + d];
    float Pre = off.x, Pim = off.y, Are = off.z, Aim = off.w;

    float pc = 0.f, ps = 0.f;
    if (t0 > 0) {
        float th = PHASE_SCALE * g_K[((size_t)(b * TT + t0 - 1)) * HD + hd];
        __sincosf(th, &ps, &pc);
    }

    size_t base = ((size_t)(b * TT + t0)) * HD + hd;
    for (int i = 0; i < LCH; i++) {
        float v  = g_V[base];
        float kr = g_K[base];
        Are += v * pc;
        Aim -= v * ps;
        float ks, kc;
        __sincosf(PHASE_SCALE * kr, &ks, &kc);
        float oa = Are * kc - Aim * ks;
        pc = kc; ps = ks;
        float sr, cr;
        sincosf((float)(t0 + i) * f, &sr, &cr);
        Pre += v * cr;
        Pim += v * sr;
        float op = Pre * cr + Pim * sr;
        int t = t0 + i;
        float o = (g0 * op + g1 * oa) * rsqrtf((float)(t + 1));
        g_ahi[base] = __half_as_ushort(__float2half_rn(o));
        base += HD;
    }
}

// ---------------------------------------------------------------------------
extern "C" void kernel_launch(void* const* d_in, const int* in_sizes, int n_in,
                              void* d_out, int out_size)
{
    const float* x     = (const float*)d_in[0];
    const float* Wk    = (const float*)d_in[1];
    const float* Wv    = (const float*)d_in[2];
    const float* Wo    = (const float*)d_in[3];
    const float* gate  = (const float*)d_in[4];
    const float* freqs = (const float*)d_in[5];
    float* out = (float*)d_out;

    float *pK, *pV;
    unsigned short *pahi, *palo, *pwT;
    cudaGetSymbolAddress((void**)&pK,   g_K);
    cudaGetSymbolAddress((void**)&pV,   g_V);
    cudaGetSymbolAddress((void**)&pahi, g_ahi);
    cudaGetSymbolAddress((void**)&palo, g_alo);
    cudaGetSymbolAddress((void**)&pwT,  g_wT);

    cudaFuncSetAttribute(gemm_t3,
                         cudaFuncAttributeMaxDynamicSharedMemorySize, GEMM_SMEM_T3);
    cudaFuncSetAttribute(gemm_t1,
                         cudaFuncAttributeMaxDynamicSharedMemorySize, GEMM_SMEM_T1);

    const int WSZ = HD * DMOD;
    unsigned short* wkh = pwT + 0*WSZ; unsigned short* wkl = pwT + 1*WSZ;
    unsigned short* wvh = pwT + 2*WSZ;
    unsigned short* woh = pwT + 4*WSZ;

    const int n4 = MROWS * HD / 4;
    split_hilo<<<(n4 + 255) / 256, 256>>>(x, pahi, palo, n4);
    wsplitT3<<<dim3(32, 32, 3), dim3(32, 8)>>>(Wk, Wv, Wo);

    dim3 ggemm(GN / BN, MROWS / BM);     // (8, 64)
    gemm_t3<<<ggemm, 256, GEMM_SMEM_T3>>>(pahi, palo, wkh, wkl, pK);  // K: 3-term
    gemm_t1<<<ggemm, 256, GEMM_SMEM_T1>>>(pahi, wvh, pV);             // V: 1-term

    int nscan = NB * NH * (NCH / 4);     // 1024
    scan_partials<<<nscan, 256>>>(freqs);
    part_prefix<<<256, 256>>>();                 // 2048 warps
    scan_final<<<nscan, 256>>>(freqs, gate);     // writes g_ahi only

    gemm_t1<<<ggemm, 256, GEMM_SMEM_T1>>>(pahi, woh, out);            // Wo: 1-term
}

// round 17
// speedup vs baseline: 1.6350x; 1.0463x over previous
#include <cuda_runtime.h>
#include <cuda_fp16.h>
#include <cstdint>
#include <math.h>

// Problem constants
#define NB   2
#define TT   4096
#define NH   16
#define ND   64
#define HD   1024
#define DMOD 1024
#define MROWS (NB*TT)       // 8192
#define PHASE_SCALE 10.0f
#define LCH  32             // chunk length for the scan
#define NCH  128            // number of chunks (LCH*NCH == TT)
#define GK   1024
#define GN   1024

// ---------------- scratch (device globals; no allocs allowed) ----------------
__device__ float  g_K [MROWS * HD];
__device__ float  g_V [MROWS * HD];
__device__ float4 g_part[NB * NH * NCH * ND];
__device__ unsigned short g_ahi[MROWS * HD];     // fp16 hi of A operand (x / OH)
__device__ unsigned short g_alo[MROWS * HD];     // fp16 lo * 256 (x only; K GEMM)
__device__ unsigned short g_wT[6][HD * DMOD];    // WkT hi/lo, WvT hi, WoT hi

// ---------------- PTX helpers (baseline sm_80+ features only) ----------------
__device__ __forceinline__ uint32_t s2u(const void* p) {
    uint32_t a;
    asm("{ .reg .u64 t; cvta.to.shared.u64 t, %1; cvt.u32.u64 %0, t; }" : "=r"(a) : "l"(p));
    return a;
}
__device__ __forceinline__ void cp16(uint32_t s, const void* g) {
    asm volatile("cp.async.cg.shared.global [%0], [%1], 16;" :: "r"(s), "l"(g));
}
__device__ __forceinline__ void cp_commit() {
    asm volatile("cp.async.commit_group;" ::: "memory");
}
template <int N>
__device__ __forceinline__ void cp_wait() {
    asm volatile("cp.async.wait_group %0;" :: "n"(N) : "memory");
}
__device__ __forceinline__ void ldsm4(uint32_t* r, uint32_t addr) {
    asm volatile("ldmatrix.sync.aligned.m8n8.x4.shared.b16 {%0,%1,%2,%3}, [%4];"
        : "=r"(r[0]), "=r"(r[1]), "=r"(r[2]), "=r"(r[3]) : "r"(addr));
}
__device__ __forceinline__ void mma_f32(float* c, const uint32_t* a, const uint32_t* b) {
    asm volatile("mma.sync.aligned.m16n8k16.row.col.f32.f16.f16.f32 "
        "{%0,%1,%2,%3}, {%4,%5,%6,%7}, {%8,%9}, {%0,%1,%2,%3};"
        : "+f"(c[0]), "+f"(c[1]), "+f"(c[2]), "+f"(c[3])
        : "r"(a[0]), "r"(a[1]), "r"(a[2]), "r"(a[3]), "r"(b[0]), "r"(b[1]));
}
__device__ __forceinline__ void mma_f16(uint32_t* c, const uint32_t* a, const uint32_t* b) {
    asm volatile("mma.sync.aligned.m16n8k16.row.col.f16.f16.f16.f16 "
        "{%0,%1}, {%2,%3,%4,%5}, {%6,%7}, {%0,%1};"
        : "+r"(c[0]), "+r"(c[1])
        : "r"(a[0]), "r"(a[1]), "r"(a[2]), "r"(a[3]), "r"(b[0]), "r"(b[1]));
}

#define BM 128
#define BN 128
#define BK 32
#define ROWB 80                       // 64B data + 16B pad
#define TILE_B  (BM * ROWB)           // 10240 B
#define NIT (GK / BK)                 // 32

// ---------------------------------------------------------------------------
// K GEMM: 3-term fp16. hi*hi (f32acc) + [hi*lo' + lo'*hi] (f16acc), lo'=lo*256.
// 4 tiles/stage, 2 stages, wait_group 0. (round-16 verbatim)
// ---------------------------------------------------------------------------
#define STAGE4 (4 * TILE_B)
#define GEMM_SMEM_T3 (2 * STAGE4)     // 81920 B

__global__ __launch_bounds__(256, 2)
void gemm_t3(const unsigned short* __restrict__ Ahi,
             const unsigned short* __restrict__ Alo,
             const unsigned short* __restrict__ Bhi,
             const unsigned short* __restrict__ Blo,
             float* __restrict__ C)
{
    extern __shared__ __align__(128) unsigned char smem[];
    const uint32_t sb = s2u(smem);

    const int tid  = threadIdx.x;
    const int lane = tid & 31;
    const int warp = tid >> 5;
    const int bm = blockIdx.y * BM;
    const int bn = blockIdx.x * BN;
    const int m0 = (warp >> 2) * 64;
    const int n0 = (warp & 3) * 32;

    const unsigned short* srcs[4] = {
        Ahi + (size_t)bm * GK, Alo + (size_t)bm * GK,
        Bhi + (size_t)bn * GK, Blo + (size_t)bn * GK };

    const int r0 = (tid + 0)   >> 2, c0i = (tid + 0)   & 3;
    const int r1 = (tid + 256) >> 2, c1i = (tid + 256) & 3;
    const uint32_t so0 = r0 * ROWB + c0i * 16;
    const uint32_t so1 = r1 * ROWB + c1i * 16;
    const size_t go0 = (size_t)r0 * GK + c0i * 8;
    const size_t go1 = (size_t)r1 * GK + c1i * 8;

    auto load_stage = [&](int s, int k0) {
        uint32_t base = sb + s * STAGE4;
        #pragma unroll
        for (int t = 0; t < 4; t++) {
            cp16(base + t * TILE_B + so0, srcs[t] + go0 + k0);
            cp16(base + t * TILE_B + so1, srcs[t] + go1 + k0);
        }
        cp_commit();
    };

    float acc[4][4][4];
    #pragma unroll
    for (int i = 0; i < 4; i++)
        #pragma unroll
        for (int j = 0; j < 4; j++)
            #pragma unroll
            for (int k = 0; k < 4; k++) acc[i][j][k] = 0.f;
    uint32_t cacc[4][4][2];
    #pragma unroll
    for (int i = 0; i < 4; i++)
        #pragma unroll
        for (int j = 0; j < 4; j++) { cacc[i][j][0] = 0u; cacc[i][j][1] = 0u; }

    const uint32_t a_off = (m0 + (lane & 15)) * ROWB + (lane >> 4) * 16;
    const uint32_t b_off = (n0 + (lane >> 4) * 8 + (lane & 7)) * ROWB
                         + ((lane >> 3) & 1) * 16;

    load_stage(0, 0);

    #pragma unroll 2
    for (int it = 0; it < NIT; it++) {
        cp_wait<0>();
        __syncthreads();
        if (it + 1 < NIT) load_stage((it + 1) & 1, (it + 1) * BK);

        const uint32_t stg = sb + (it & 1) * STAGE4;
        const uint32_t sAh = stg + a_off;
        const uint32_t sAl = stg + TILE_B + a_off;
        const uint32_t sBh = stg + 2 * TILE_B + b_off;
        const uint32_t sBl = stg + 3 * TILE_B + b_off;

        #pragma unroll
        for (int kk = 0; kk < 2; kk++) {
            const uint32_t kb = kk * 32;
            uint32_t bh[8], bl[8];
            ldsm4(bh + 0, sBh + kb);
            ldsm4(bh + 4, sBh + kb + 16 * ROWB);
            ldsm4(bl + 0, sBl + kb);
            ldsm4(bl + 4, sBl + kb + 16 * ROWB);
            #pragma unroll
            for (int mt = 0; mt < 4; mt++) {
                uint32_t ah[4];
                ldsm4(ah, sAh + kb + mt * (16 * ROWB));
                #pragma unroll
                for (int nt = 0; nt < 4; nt++)       // hi*hi -> f32 acc
                    mma_f32(acc[mt][nt], ah, bh + (nt >> 1) * 4 + (nt & 1) * 2);
                #pragma unroll
                for (int nt = 0; nt < 4; nt++)       // hi*lo' -> f16 acc
                    mma_f16(cacc[mt][nt], ah, bl + (nt >> 1) * 4 + (nt & 1) * 2);
                uint32_t al[4];
                ldsm4(al, sAl + kb + mt * (16 * ROWB));
                #pragma unroll
                for (int nt = 0; nt < 4; nt++)       // lo'*hi -> f16 acc
                    mma_f16(cacc[mt][nt], al, bh + (nt >> 1) * 4 + (nt & 1) * 2);
            }
        }
    }

    const float cs = 1.0f / 256.0f;
    #pragma unroll
    for (int mt = 0; mt < 4; mt++) {
        const int m = bm + m0 + mt * 16 + (lane >> 2);
        #pragma unroll
        for (int nt = 0; nt < 4; nt++) {
            const int n = bn + n0 + nt * 8 + (lane & 3) * 2;
            float2 c0 = __half22float2(*(__half2*)&cacc[mt][nt][0]);
            float2 c1 = __half22float2(*(__half2*)&cacc[mt][nt][1]);
            *(float2*)&C[(size_t)m * GN + n] =
                make_float2(acc[mt][nt][0] + cs * c0.x,
                            acc[mt][nt][1] + cs * c0.y);
            *(float2*)&C[(size_t)(m + 8) * GN + n] =
                make_float2(acc[mt][nt][2] + cs * c1.x,
                            acc[mt][nt][3] + cs * c1.y);
        }
    }
}

// ---------------------------------------------------------------------------
// 1-term GEMM (V, Wo): hi*hi -> f32acc. 2 tiles/stage, 3 stages, wait 1.
// ---------------------------------------------------------------------------
#define STAGE2 (2 * TILE_B)
#define GEMM_SMEM_T1 (3 * STAGE2)     // 61440 B

__global__ __launch_bounds__(256, 2)
void gemm_t1(const unsigned short* __restrict__ Ahi,
             const unsigned short* __restrict__ Bhi,
             float* __restrict__ C)
{
    extern __shared__ __align__(128) unsigned char smem[];
    const uint32_t sb = s2u(smem);

    const int tid  = threadIdx.x;
    const int lane = tid & 31;
    const int warp = tid >> 5;
    const int bm = blockIdx.y * BM;
    const int bn = blockIdx.x * BN;
    const int m0 = (warp >> 2) * 64;
    const int n0 = (warp & 3) * 32;

    const unsigned short* srcs[2] = {
        Ahi + (size_t)bm * GK, Bhi + (size_t)bn * GK };

    const int r0 = (tid + 0)   >> 2, c0i = (tid + 0)   & 3;
    const int r1 = (tid + 256) >> 2, c1i = (tid + 256) & 3;
    const uint32_t so0 = r0 * ROWB + c0i * 16;
    const uint32_t so1 = r1 * ROWB + c1i * 16;
    const size_t go0 = (size_t)r0 * GK + c0i * 8;
    const size_t go1 = (size_t)r1 * GK + c1i * 8;

    auto load_stage = [&](int s, int k0) {
        uint32_t base = sb + s * STAGE2;
        #pragma unroll
        for (int t = 0; t < 2; t++) {
            cp16(base + t * TILE_B + so0, srcs[t] + go0 + k0);
            cp16(base + t * TILE_B + so1, srcs[t] + go1 + k0);
        }
        cp_commit();
    };

    float acc[4][4][4];
    #pragma unroll
    for (int i = 0; i < 4; i++)
        #pragma unroll
        for (int j = 0; j < 4; j++)
            #pragma unroll
            for (int k = 0; k < 4; k++) acc[i][j][k] = 0.f;

    const uint32_t a_off = (m0 + (lane & 15)) * ROWB + (lane >> 4) * 16;
    const uint32_t b_off = (n0 + (lane >> 4) * 8 + (lane & 7)) * ROWB
                         + ((lane >> 3) & 1) * 16;

    load_stage(0, 0);
    load_stage(1, BK);

    int s_cur = 0;
    for (int it = 0; it < NIT; it++) {
        cp_wait<1>();
        __syncthreads();
        if (it + 2 < NIT) {
            int s_nx = s_cur + 2; if (s_nx >= 3) s_nx -= 3;
            load_stage(s_nx, (it + 2) * BK);
        }

        const uint32_t stg = sb + s_cur * STAGE2;
        const uint32_t sAh = stg + a_off;
        const uint32_t sBh = stg + TILE_B + b_off;

        #pragma unroll
        for (int kk = 0; kk < 2; kk++) {
            const uint32_t kb = kk * 32;
            uint32_t bh[8];
            ldsm4(bh + 0, sBh + kb);
            ldsm4(bh + 4, sBh + kb + 16 * ROWB);
            #pragma unroll
            for (int mt = 0; mt < 4; mt++) {
                uint32_t ah[4];
                ldsm4(ah, sAh + kb + mt * (16 * ROWB));
                #pragma unroll
                for (int nt = 0; nt < 4; nt++)
                    mma_f32(acc[mt][nt], ah, bh + (nt >> 1) * 4 + (nt & 1) * 2);
            }
        }
        if (++s_cur == 3) s_cur = 0;
    }

    #pragma unroll
    for (int mt = 0; mt < 4; mt++) {
        const int m = bm + m0 + mt * 16 + (lane >> 2);
        #pragma unroll
        for (int nt = 0; nt < 4; nt++) {
            const int n = bn + n0 + nt * 8 + (lane & 3) * 2;
            *(float2*)&C[(size_t)m * GN + n] =
                make_float2(acc[mt][nt][0], acc[mt][nt][1]);
            *(float2*)&C[(size_t)(m + 8) * GN + n] =
                make_float2(acc[mt][nt][2], acc[mt][nt][3]);
        }
    }
}

// ---------------------------------------------------------------------------
// fp32 -> fp16 hi + (lo*256) split helpers
// ---------------------------------------------------------------------------
__device__ __forceinline__ unsigned short f16_hi(float x, float& rem) {
    __half h = __float2half_rn(x);
    rem = x - __half2float(h);
    return __half_as_ushort(h);
}
__device__ __forceinline__ unsigned short f16_lo256(float rem) {
    return __half_as_ushort(__float2half_rn(rem * 256.0f));
}

__global__ void split_hilo(const float* __restrict__ src,
                           unsigned short* __restrict__ hi,
                           unsigned short* __restrict__ lo, int n4)
{
    int i = blockIdx.x * blockDim.x + threadIdx.x;
    if (i >= n4) return;
    float4 v = ((const float4*)src)[i];
    float r0, r1, r2, r3;
    unsigned short h0 = f16_hi(v.x, r0), h1 = f16_hi(v.y, r1);
    unsigned short h2 = f16_hi(v.z, r2), h3 = f16_hi(v.w, r3);
    ((uint2*)hi)[i] = make_uint2((uint32_t)h0 | ((uint32_t)h1 << 16),
                                (uint32_t)h2 | ((uint32_t)h3 << 16));
    unsigned short l0 = f16_lo256(r0), l1 = f16_lo256(r1);
    unsigned short l2 = f16_lo256(r2), l3 = f16_lo256(r3);
    ((uint2*)lo)[i] = make_uint2((uint32_t)l0 | ((uint32_t)l1 << 16),
                                (uint32_t)l2 | ((uint32_t)l3 << 16));
}

// W [K,N] fp32 -> WT [N,K] fp16; lo written only for Wk (z==0)
__global__ void wsplitT3(const float* __restrict__ W0,
                         const float* __restrict__ W1,
                         const float* __restrict__ W2)
{
    __shared__ float tile[32][33];
    const float* W = (blockIdx.z == 0) ? W0 : (blockIdx.z == 1) ? W1 : W2;
    unsigned short* hiT = &g_wT[2 * blockIdx.z][0];
    unsigned short* loT = &g_wT[2 * blockIdx.z + 1][0];
    int n0 = blockIdx.x * 32, k0 = blockIdx.y * 32;
    int tx = threadIdx.x, ty = threadIdx.y;
    for (int r = ty; r < 32; r += 8)
        tile[r][tx] = W[(size_t)(k0 + r) * GN + n0 + tx];
    __syncthreads();
    for (int r = ty; r < 32; r += 8) {
        float v = tile[tx][r];
        size_t o = (size_t)(n0 + r) * GK + k0 + tx;
        float rem;
        hiT[o] = f16_hi(v, rem);
        if (blockIdx.z == 0) loT[o] = f16_lo256(rem);
    }
}

// ---------------------------------------------------------------------------
// Scan pass A: per-chunk partial complex sums.
// ---------------------------------------------------------------------------
__global__ void scan_partials(const float* __restrict__ freqs)
{
    const int tid = threadIdx.x;
    const int d   = tid & 63;
    const int sub = tid >> 6;
    const int bh  = blockIdx.x >> 5;
    const int cg  = blockIdx.x & 31;
    const int c   = cg * 4 + sub;
    const int b   = bh >> 4;
    const int h   = bh & 15;
    const int t0 = c * LCH;
    const int hd = h * ND + d;

    const float f = freqs[hd];

    float pc = 0.f, ps = 0.f;
    if (t0 > 0) {
        float th = PHASE_SCALE * g_K[((size_t)(b * TT + t0 - 1)) * HD + hd];
        __sincosf(th, &ps, &pc);
    }

    float Pre = 0.f, Pim = 0.f, Are = 0.f, Aim = 0.f;
    size_t base = ((size_t)(b * TT + t0)) * HD + hd;
    for (int i = 0; i < LCH; i++) {
        float v  = g_V[base];
        float kr = g_K[base];
        base += HD;
        Are += v * pc;
        Aim -= v * ps;
        float ks, kc;
        __sincosf(PHASE_SCALE * kr, &ks, &kc);
        pc = kc; ps = ks;
        float sr, cr;
        sincosf((float)(t0 + i) * f, &sr, &cr);
        Pre += v * cr;
        Pim += v * sr;
    }
    g_part[((size_t)bh * NCH + c) * ND + d] = make_float4(Pre, Pim, Are, Aim);
}

// ---------------------------------------------------------------------------
// Convert g_part to EXCLUSIVE prefix along the chunk axis (in place).
// ---------------------------------------------------------------------------
__global__ void part_prefix()
{
    const int gw   = (blockIdx.x * blockDim.x + threadIdx.x) >> 5;  // 0..2047
    const int lane = threadIdx.x & 31;
    if (gw >= 32 * ND) return;
    const int bh = gw >> 6;
    const int d  = gw & 63;
    float4* p = g_part + (size_t)bh * NCH * ND + d;

    float4 carry = make_float4(0.f, 0.f, 0.f, 0.f);
    #pragma unroll
    for (int r = 0; r < 4; r++) {
        const int c = r * 32 + lane;
        float4 v = p[(size_t)c * ND];
        float4 incl = v;
        #pragma unroll
        for (int ofs = 1; ofs < 32; ofs <<= 1) {
            float ax = __shfl_up_sync(0xffffffffu, incl.x, ofs);
            float ay = __shfl_up_sync(0xffffffffu, incl.y, ofs);
            float az = __shfl_up_sync(0xffffffffu, incl.z, ofs);
            float aw = __shfl_up_sync(0xffffffffu, incl.w, ofs);
            if (lane >= ofs) { incl.x += ax; incl.y += ay; incl.z += az; incl.w += aw; }
        }
        float4 excl = make_float4(incl.x - v.x + carry.x, incl.y - v.y + carry.y,
                                  incl.z - v.z + carry.z, incl.w - v.w + carry.w);
        p[(size_t)c * ND] = excl;
        carry.x += __shfl_sync(0xffffffffu, incl.x, 31);
        carry.y += __shfl_sync(0xffffffffu, incl.y, 31);
        carry.z += __shfl_sync(0xffffffffu, incl.z, 31);
        carry.w += __shfl_sync(0xffffffffu, incl.w, 31);
    }
}

// ---------------------------------------------------------------------------
// Scan pass B: single exclusive-offset load + final gated output -> fp16 hi
// ---------------------------------------------------------------------------
__global__ void scan_final(const float* __restrict__ freqs,
                           const float* __restrict__ gate)
{
    const int tid = threadIdx.x;
    const int d   = tid & 63;
    const int sub = tid >> 6;
    const int bh  = blockIdx.x >> 5;
    const int cg  = blockIdx.x & 31;
    const int c   = cg * 4 + sub;
    const int b   = bh >> 4;
    const int h   = bh & 15;
    const int hd  = h * ND + d;

    const float f  = freqs[hd];
    const float g0 = gate[2 * h];
    const float g1 = gate[2 * h + 1];
    const int t0 = c * LCH;

    float4 off = g_part[((size_t)bh * NCH + c) * ND + d];
    float Pre = off.x, Pim = off.y, Are = off.z, Aim = off.w;

    float pc = 0.f, ps = 0.f;
    if (t0 > 0) {
        float th = PHASE_SCALE * g_K[((size_t)(b * TT + t0 - 1)) * HD + hd];
        __sincosf(th, &ps, &pc);
    }

    size_t base = ((size_t)(b * TT + t0)) * HD + hd;
    for (int i = 0; i < LCH; i++) {
        float v  = g_V[base];
        float kr = g_K[base];
        Are += v * pc;
        Aim -= v * ps;
        float ks, kc;
        __sincosf(PHASE_SCALE * kr, &ks, &kc);
        float oa = Are * kc - Aim * ks;
        pc = kc; ps = ks;
        float sr, cr;
        sincosf((float)(t0 + i) * f, &sr, &cr);
        Pre += v * cr;
        Pim += v * sr;
        float op = Pre * cr + Pim * sr;
        int t = t0 + i;
        float o = (g0 * op + g1 * oa) * rsqrtf((float)(t + 1));
        g_ahi[base] = __half_as_ushort(__float2half_rn(o));
        base += HD;
    }
}

// ---------------------------------------------------------------------------
extern "C" void kernel_launch(void* const* d_in, const int* in_sizes, int n_in,
                              void* d_out, int out_size)
{
    const float* x     = (const float*)d_in[0];
    const float* Wk    = (const float*)d_in[1];
    const float* Wv    = (const float*)d_in[2];
    const float* Wo    = (const float*)d_in[3];
    const float* gate  = (const float*)d_in[4];
    const float* freqs = (const float*)d_in[5];
    float* out = (float*)d_out;

    float *pK, *pV;
    unsigned short *pahi, *palo, *pwT;
    cudaGetSymbolAddress((void**)&pK,   g_K);
    cudaGetSymbolAddress((void**)&pV,   g_V);
    cudaGetSymbolAddress((void**)&pahi, g_ahi);
    cudaGetSymbolAddress((void**)&palo, g_alo);
    cudaGetSymbolAddress((void**)&pwT,  g_wT);

    cudaFuncSetAttribute(gemm_t3,
                         cudaFuncAttributeMaxDynamicSharedMemorySize, GEMM_SMEM_T3);
    cudaFuncSetAttribute(gemm_t1,
                         cudaFuncAttributeMaxDynamicSharedMemorySize, GEMM_SMEM_T1);

    const int WSZ = HD * DMOD;
    unsigned short* wkh = pwT + 0*WSZ; unsigned short* wkl = pwT + 1*WSZ;
    unsigned short* wvh = pwT + 2*WSZ;
    unsigned short* woh = pwT + 4*WSZ;

    // Side stream + events for graph-forked concurrency. Host-side objects
    // only (no device memory); kernel_launch runs exactly twice (correctness
    // + capture), so the unconditional creates are bounded.
    cudaStream_t s1;
    cudaStreamCreate(&s1);
    cudaEvent_t eRoot, eS, eW, eV;
    cudaEventCreateWithFlags(&eRoot, cudaEventDisableTiming);
    cudaEventCreateWithFlags(&eS,    cudaEventDisableTiming);
    cudaEventCreateWithFlags(&eW,    cudaEventDisableTiming);
    cudaEventCreateWithFlags(&eV,    cudaEventDisableTiming);

    const int n4 = MROWS * HD / 4;

    // fork s1 off the (possibly capturing) default stream
    cudaEventRecord(eRoot, 0);
    cudaStreamWaitEvent(s1, eRoot, 0);

    // s1: weight transpose/split  ||  s0: activation split
    wsplitT3<<<dim3(32, 32, 3), dim3(32, 8), 0, s1>>>(Wk, Wv, Wo);
    cudaEventRecord(eW, s1);
    split_hilo<<<(n4 + 255) / 256, 256>>>(x, pahi, palo, n4);
    cudaEventRecord(eS, 0);

    // s0: K GEMM (needs split + wsplit)   ||   s1: V GEMM (needs split + wsplit)
    cudaStreamWaitEvent(0, eW, 0);
    dim3 ggemm(GN / BN, MROWS / BM);     // (8, 64)
    gemm_t3<<<ggemm, 256, GEMM_SMEM_T3>>>(pahi, palo, wkh, wkl, pK);  // K: 3-term
    cudaStreamWaitEvent(s1, eS, 0);
    gemm_t1<<<ggemm, 256, GEMM_SMEM_T1, s1>>>(pahi, wvh, pV);         // V: 1-term
    cudaEventRecord(eV, s1);

    // s0: join V, then scans + Wo
    cudaStreamWaitEvent(0, eV, 0);
    int nscan = NB * NH * (NCH / 4);     // 1024
    scan_partials<<<nscan, 256>>>(freqs);
    part_prefix<<<256, 256>>>();
    scan_final<<<nscan, 256>>>(freqs, gate);

    gemm_t1<<<ggemm, 256, GEMM_SMEM_T1>>>(pahi, woh, out);            // Wo: 1-term

    cudaStreamDestroy(s1);   // async-safe: work already enqueued/captured
}